// round 16
// baseline (speedup 1.0000x reference)
#include <cuda_runtime.h>
#include <cuda_fp16.h>
#include <cstdint>

#define IN_DIM  4096
#define OUT_DIM 4096
#define RANK    16
#define RTOT    80
#define SCALING 2.0f

#define MTOK    8192
#define KPAD    4224        // 4096 + 128 tail (80 used + 48 zero pad)
#define BK      64
#define NKT     (KPAD / BK) // 66

#define MCH0    2048        // small first chunk: unblocks GEMM-0 early
#define MCH1    (MTOK - MCH0)   // 6144: chain hides under GEMM-0

// main GEMM (R4 proven, FROZEN): 128x128 CTA, 8 warps (64x32), 3 stages
#define ASTAGE      16384
#define STAGE_BYTES 32768
#define SMEM_DYN    (3 * STAGE_BYTES)     // 98304 -> 2 CTAs/SM

// prep GEMM: 64x128 CTA tile, 3 stages, K-split 4
#define P_ASTAGE 8192
#define P_STAGE  24576
#define P_SMEM   (3 * P_STAGE)            // 73728
#define KSPLIT   4
#define PKT      ((IN_DIM / BK) / KSPLIT) // 16 kts per split

// ---------------- scratch ----------------------------------------------------
__device__ __align__(16) __half g_a16[(size_t)MTOK    * KPAD];
__device__ __align__(16) __half g_b16[(size_t)OUT_DIM * KPAD];
__device__ __align__(16) __half g_w16[(size_t)128 * IN_DIM];
__device__ __align__(16) float  g_dotp[(size_t)KSPLIT * MTOK * 128];

// ---------------- PTX helpers ------------------------------------------------
__device__ __forceinline__ uint32_t smem_u32(const void* p) {
    uint32_t a;
    asm("{ .reg .u64 t; cvta.to.shared.u64 t, %1; cvt.u32.u64 %0, t; }" : "=r"(a) : "l"(p));
    return a;
}
__device__ __forceinline__ void cp16(uint32_t dst, const void* src) {
    asm volatile("cp.async.cg.shared.global [%0], [%1], 16;" :: "r"(dst), "l"(src));
}
__device__ __forceinline__ void cp_commit() {
    asm volatile("cp.async.commit_group;" ::: "memory");
}
__device__ __forceinline__ void cp_wait1() {
    asm volatile("cp.async.wait_group 1;" ::: "memory");
}
__device__ __forceinline__ void ldsm4(uint32_t* r, uint32_t addr) {
    asm volatile("ldmatrix.sync.aligned.m8n8.x4.shared.b16 {%0,%1,%2,%3}, [%4];"
                 : "=r"(r[0]), "=r"(r[1]), "=r"(r[2]), "=r"(r[3]) : "r"(addr));
}
__device__ __forceinline__ void mma16816(float* d, const uint32_t* a, const uint32_t* b) {
    asm volatile(
        "mma.sync.aligned.m16n8k16.row.col.f32.f16.f16.f32 "
        "{%0,%1,%2,%3}, {%4,%5,%6,%7}, {%8,%9}, {%0,%1,%2,%3};"
        : "+f"(d[0]), "+f"(d[1]), "+f"(d[2]), "+f"(d[3])
        : "r"(a[0]), "r"(a[1]), "r"(a[2]), "r"(a[3]), "r"(b[0]), "r"(b[1]));
}
__device__ __forceinline__ uint4 pack8_h(const float* v) {
    __half2 h01 = __floats2half2_rn(v[0], v[1]);
    __half2 h23 = __floats2half2_rn(v[2], v[3]);
    __half2 h45 = __floats2half2_rn(v[4], v[5]);
    __half2 h67 = __floats2half2_rn(v[6], v[7]);
    uint4 u;
    u.x = *reinterpret_cast<uint32_t*>(&h01);
    u.y = *reinterpret_cast<uint32_t*>(&h23);
    u.z = *reinterpret_cast<uint32_t*>(&h45);
    u.w = *reinterpret_cast<uint32_t*>(&h67);
    return u;
}

// ---------------------------------------------------------------------------
// conv_w: [A|subA|gate] -> g_w16
// ---------------------------------------------------------------------------
#define NCHUNK_W (128 * 512)
__global__ __launch_bounds__(256) void conv_w_kernel(
    const float* __restrict__ base_A,
    const float* __restrict__ sub_A,
    const float* __restrict__ sub_wgate)
{
    int id  = blockIdx.x * 256 + threadIdx.x;
    int row = id >> 9;
    int k   = (id & 511) * 8;
    const float* src = nullptr;
    if (row < 16)      src = &base_A[(size_t)row * IN_DIM + k];
    else if (row < 80) src = &sub_A[(size_t)(row - 16) * IN_DIM + k];
    else if (row < 84) src = &sub_wgate[(size_t)(row - 80) * IN_DIM + k];
    float v[8];
    if (src) {
        float4 v0 = *(const float4*)src;
        float4 v1 = *(const float4*)(src + 4);
        v[0]=v0.x; v[1]=v0.y; v[2]=v0.z; v[3]=v0.w;
        v[4]=v1.x; v[5]=v1.y; v[6]=v1.z; v[7]=v1.w;
    } else {
        #pragma unroll
        for (int q = 0; q < 8; ++q) v[q] = 0.f;
    }
    *(uint4*)&g_w16[(size_t)row * IN_DIM + k] = pack8_h(v);
}

// ---------------------------------------------------------------------------
// conv_b: [W|base_B|sub_B|0] -> g_b16   (side stream, overlaps chain-0)
// ---------------------------------------------------------------------------
#define NCHUNK_B (OUT_DIM * 528)
__global__ __launch_bounds__(256) void conv_b_kernel(
    const float* __restrict__ W,
    const float* __restrict__ base_B,
    const float* __restrict__ sub_B)
{
    int id = blockIdx.x * 256 + threadIdx.x;
    if (id >= NCHUNK_B) return;
    int n = id / 528;
    int k = (id - n * 528) * 8;
    const float* src = nullptr;
    if (k < IN_DIM) {
        src = &W[(size_t)n * IN_DIM + k];
    } else if (k < IN_DIM + RANK) {
        src = &base_B[(size_t)n * RANK + (k - IN_DIM)];
    } else if (k < IN_DIM + RTOT) {
        int kk = k - IN_DIM - RANK;
        int j  = kk >> 4;
        int rr = kk & 15;
        src = &sub_B[((size_t)j * OUT_DIM + n) * RANK + rr];
    }
    float v[8];
    if (src) {
        float4 v0 = *(const float4*)src;
        float4 v1 = *(const float4*)(src + 4);
        v[0]=v0.x; v[1]=v0.y; v[2]=v0.z; v[3]=v0.w;
        v[4]=v1.x; v[5]=v1.y; v[6]=v1.z; v[7]=v1.w;
    } else {
        #pragma unroll
        for (int q = 0; q < 8; ++q) v[q] = 0.f;
    }
    *(uint4*)&g_b16[(size_t)n * KPAD + k] = pack8_h(v);
}

// ---------------------------------------------------------------------------
// conv_a chunk: x[m0 : m0 + grid*256/512] -> fp16 main columns of g_a16
// ---------------------------------------------------------------------------
__global__ __launch_bounds__(256) void conv_a_kernel(const float* __restrict__ x, int m0)
{
    int id = blockIdx.x * 256 + threadIdx.x;
    int m  = m0 + (id >> 9);
    int k  = (id & 511) * 8;
    float v[8];
    float4 v0 = *(const float4*)&x[(size_t)m * IN_DIM + k];
    float4 v1 = *(const float4*)&x[(size_t)m * IN_DIM + k + 4];
    v[0]=v0.x; v[1]=v0.y; v[2]=v0.z; v[3]=v0.w;
    v[4]=v1.x; v[5]=v1.y; v[6]=v1.z; v[7]=v1.w;
    *(uint4*)&g_a16[(size_t)m * KPAD + k] = pack8_h(v);
}

// ---------------------------------------------------------------------------
// prep_hmma chunk, K-split x4: partial dots for tokens [m0, m0 + 64*grid.x)
// ---------------------------------------------------------------------------
__global__ __launch_bounds__(256, 2) void prep_hmma(int m0)
{
    extern __shared__ __align__(1024) char smem[];
    const uint32_t sb = smem_u32(smem);

    const int tid  = threadIdx.x;
    const int lane = tid & 31;
    const int wid  = tid >> 5;
    const int bm   = m0 + blockIdx.x * 64;
    const int sp   = blockIdx.y;
    const int kt0  = sp * PKT;
    const int wm   = (wid & 1) * 32;
    const int wn   = (wid >> 1) * 32;

    float acc[2][4][4];
    #pragma unroll
    for (int mi = 0; mi < 2; ++mi)
        #pragma unroll
        for (int ni = 0; ni < 4; ++ni)
            #pragma unroll
            for (int q = 0; q < 4; ++q) acc[mi][ni][q] = 0.f;

    const char* gA = (const char*)(g_a16 + (size_t)bm * KPAD);
    const char* gW = (const char*)g_w16;
    const size_t arow_b = (size_t)KPAD * 2;
    const size_t wrow_b = (size_t)IN_DIM * 2;

    const int a_row = tid >> 2;
    const int a_col = (tid & 3) * 16;
    const int b_row = tid >> 1;
    const int b_col = (tid & 1) * 16;

    const int arow  = wm + (lane & 15);
    const int akoff = (lane >> 4) * 16;
    const int apx   = (arow & 7) << 4;
    const int bmat  = lane >> 3;
    const int brow  = wn + (bmat >> 1) * 8 + (lane & 7);
    const int bkoff = (bmat & 1) * 16;
    const int bpx   = (brow & 7) << 4;

#define P_LOAD(s, kt)                                                          \
    {                                                                          \
        const int kb = (kt0 + (kt)) * (BK * 2);                                \
        _Pragma("unroll")                                                      \
        for (int i = 0; i < 2; ++i) {                                          \
            int cb = a_col + i * 64;                                           \
            uint32_t off = a_row * 128 + cb;                                   \
            uint32_t sw  = off ^ ((off >> 3) & 0x70);                          \
            cp16(sb + (s) * P_STAGE + sw, gA + (size_t)a_row * arow_b + kb + cb); \
        }                                                                      \
        _Pragma("unroll")                                                      \
        for (int i = 0; i < 4; ++i) {                                          \
            int cb = b_col + i * 32;                                           \
            uint32_t off = b_row * 128 + cb;                                   \
            uint32_t sw  = off ^ ((off >> 3) & 0x70);                          \
            cp16(sb + (s) * P_STAGE + P_ASTAGE + sw,                           \
                 gW + (size_t)b_row * wrow_b + kb + cb);                       \
        }                                                                      \
        cp_commit();                                                           \
    }

    P_LOAD(0, 0);
    P_LOAD(1, 1);

    for (int kt = 0; kt < PKT; ++kt) {
        cp_wait1();
        __syncthreads();
        if (kt + 2 < PKT) {
            P_LOAD((kt + 2) % 3, kt + 2);
        } else {
            cp_commit();
        }

        const uint32_t sa = sb + (kt % 3) * P_STAGE;
        const uint32_t sB = sa + P_ASTAGE;

        #pragma unroll
        for (int ks = 0; ks < 4; ++ks) {
            const int kb = ks * 32;
            uint32_t a[2][4], b[2][4];
            #pragma unroll
            for (int mi = 0; mi < 2; ++mi)
                ldsm4(a[mi], sa + (uint32_t)(arow + mi * 16) * 128 +
                             (uint32_t)((kb + akoff) ^ apx));
            #pragma unroll
            for (int g = 0; g < 2; ++g)
                ldsm4(b[g], sB + (uint32_t)(brow + g * 16) * 128 +
                            (uint32_t)((kb + bkoff) ^ bpx));
            #pragma unroll
            for (int mi = 0; mi < 2; ++mi) {
                mma16816(acc[mi][0], a[mi], &b[0][0]);
                mma16816(acc[mi][1], a[mi], &b[0][2]);
                mma16816(acc[mi][2], a[mi], &b[1][0]);
                mma16816(acc[mi][3], a[mi], &b[1][2]);
            }
        }
    }
#undef P_LOAD

    float* dout = g_dotp + (size_t)sp * MTOK * 128;
    const int g8 = lane >> 2;
    const int t4 = lane & 3;
    #pragma unroll
    for (int ni = 0; ni < 4; ++ni) {
        const int n = wn + ni * 8 + t4 * 2;
        #pragma unroll
        for (int mi = 0; mi < 2; ++mi) {
            const int m = bm + wm + mi * 16 + g8;
            *(float2*)&dout[(size_t)m * 128 + n]       = make_float2(acc[mi][ni][0], acc[mi][ni][1]);
            *(float2*)&dout[(size_t)(m + 8) * 128 + n] = make_float2(acc[mi][ni][2], acc[mi][ni][3]);
        }
    }
}

// ---------------------------------------------------------------------------
// combine chunk (vectorized): sum partials, gate, write fp16 tail of g_a16
// ---------------------------------------------------------------------------
__global__ __launch_bounds__(256) void combine_kernel(int m0)
{
    int id  = blockIdx.x * 256 + threadIdx.x;
    int m   = m0 + (id >> 5);
    int col = (id & 31) * 4;

    __half hv[4];
    if (col < RTOT) {
        float4 d = make_float4(0.f, 0.f, 0.f, 0.f);
        #pragma unroll
        for (int s = 0; s < KSPLIT; ++s) {
            float4 p = *(const float4*)&g_dotp[(size_t)s * MTOK * 128 +
                                               (size_t)m * 128 + col];
            d.x += p.x; d.y += p.y; d.z += p.z; d.w += p.w;
        }
        float gmul = 1.f;
        if (col >= RANK) {
            int gc = 80 + ((col - RANK) >> 4);
            float gt = 0.f;
            #pragma unroll
            for (int s = 0; s < KSPLIT; ++s)
                gt += g_dotp[(size_t)s * MTOK * 128 + (size_t)m * 128 + gc];
            gmul = gt > 0.f ? gt : 0.f;
        }
        const float f = SCALING * gmul;
        hv[0] = __float2half(d.x * f);
        hv[1] = __float2half(d.y * f);
        hv[2] = __float2half(d.z * f);
        hv[3] = __float2half(d.w * f);
    } else {
        hv[0] = hv[1] = hv[2] = hv[3] = __float2half(0.f);
    }
    *(uint2*)&g_a16[(size_t)m * KPAD + IN_DIM + col] = *reinterpret_cast<uint2*>(hv);
}

// ---------------------------------------------------------------------------
// Main HMMA GEMM chunk — FROZEN R4 config, with M offset
// ---------------------------------------------------------------------------
__global__ __launch_bounds__(256, 2) void lora_gemm_hmma(
    const float* __restrict__ bias,
    float* __restrict__ out,
    int m0)
{
    extern __shared__ __align__(1024) char smem[];
    const uint32_t sb = smem_u32(smem);

    const int tid  = threadIdx.x;
    const int lane = tid & 31;
    const int wid  = tid >> 5;
    const int bm   = m0 + blockIdx.y * 128;
    const int bn   = blockIdx.x * 128;
    const int wm   = (wid & 1) * 64;
    const int wn   = (wid >> 1) * 32;

    float acc[4][4][4];
    #pragma unroll
    for (int mi = 0; mi < 4; ++mi)
        #pragma unroll
        for (int ni = 0; ni < 4; ++ni)
            #pragma unroll
            for (int q = 0; q < 4; ++q) acc[mi][ni][q] = 0.f;

    const char* gA = (const char*)(g_a16 + (size_t)bm * KPAD);
    const char* gB = (const char*)(g_b16 + (size_t)bn * KPAD);
    const size_t rowbytes = (size_t)KPAD * 2;

    const int crow = tid >> 3;
    const int ccol = (tid & 7) * 16;

    const int arow  = wm + (lane & 15);
    const int akoff = (lane >> 4) * 16;
    const int apx   = (arow & 7) << 4;
    const int bmat  = lane >> 3;
    const int brow  = wn + (bmat >> 1) * 8 + (lane & 7);
    const int bkoff = (bmat & 1) * 16;
    const int bpx   = (brow & 7) << 4;

#define LOAD_STAGE(s, kt)                                                      \
    {                                                                          \
        const int kb = (kt) * (BK * 2);                                        \
        _Pragma("unroll")                                                      \
        for (int i = 0; i < 4; ++i) {                                          \
            int row = crow + i * 32;                                           \
            uint32_t off = row * 128 + ccol;                                   \
            uint32_t sw  = off ^ ((off >> 3) & 0x70);                          \
            cp16(sb + (s) * STAGE_BYTES + sw, gA + (size_t)row * rowbytes + kb + ccol); \
            cp16(sb + (s) * STAGE_BYTES + ASTAGE + sw,                         \
                 gB + (size_t)row * rowbytes + kb + ccol);                     \
        }                                                                      \
        cp_commit();                                                           \
    }

    LOAD_STAGE(0, 0);
    LOAD_STAGE(1, 1);

    for (int kt = 0; kt < NKT; ++kt) {
        cp_wait1();
        __syncthreads();
        if (kt + 2 < NKT) {
            LOAD_STAGE((kt + 2) % 3, kt + 2);
        } else {
            cp_commit();
        }

        const uint32_t sa = sb + (kt % 3) * STAGE_BYTES;
        const uint32_t sB = sa + ASTAGE;

        #pragma unroll
        for (int ks = 0; ks < 4; ++ks) {
            const int kb = ks * 32;
            uint32_t a[4][4], b[2][4];
            #pragma unroll
            for (int mi = 0; mi < 4; ++mi)
                ldsm4(a[mi], sa + (uint32_t)(arow + mi * 16) * 128 +
                             (uint32_t)((kb + akoff) ^ apx));
            #pragma unroll
            for (int g = 0; g < 2; ++g)
                ldsm4(b[g], sB + (uint32_t)(brow + g * 16) * 128 +
                            (uint32_t)((kb + bkoff) ^ bpx));
            #pragma unroll
            for (int mi = 0; mi < 4; ++mi) {
                mma16816(acc[mi][0], a[mi], &b[0][0]);
                mma16816(acc[mi][1], a[mi], &b[0][2]);
                mma16816(acc[mi][2], a[mi], &b[1][0]);
                mma16816(acc[mi][3], a[mi], &b[1][2]);
            }
        }
    }
#undef LOAD_STAGE

    const int g8 = lane >> 2;
    const int t4 = lane & 3;
    #pragma unroll
    for (int ni = 0; ni < 4; ++ni) {
        const int n = bn + wn + ni * 8 + t4 * 2;
        const float2 bv = *(const float2*)&bias[n];
        #pragma unroll
        for (int mi = 0; mi < 4; ++mi) {
            const int m = bm + wm + mi * 16 + g8;
            float2 o0, o1;
            o0.x = acc[mi][ni][0] + bv.x;
            o0.y = acc[mi][ni][1] + bv.y;
            o1.x = acc[mi][ni][2] + bv.x;
            o1.y = acc[mi][ni][3] + bv.y;
            *(float2*)&out[(size_t)m * OUT_DIM + n]       = o0;
            *(float2*)&out[(size_t)(m + 8) * OUT_DIM + n] = o1;
        }
    }
}

// ---------------------------------------------------------------------------
extern "C" void kernel_launch(void* const* d_in, const int* in_sizes, int n_in,
                              void* d_out, int out_size)
{
    const float* x         = (const float*)d_in[0];
    const float* base_W    = (const float*)d_in[1];
    const float* base_b    = (const float*)d_in[2];
    const float* base_A    = (const float*)d_in[3];
    const float* base_B    = (const float*)d_in[4];
    const float* sub_wgate = (const float*)d_in[5];
    const float* sub_A     = (const float*)d_in[6];
    const float* sub_B     = (const float*)d_in[7];
    float* out = (float*)d_out;

    static cudaStream_t s1 = nullptr;          // single extra stream (guard-safe)
    static cudaEvent_t  ev0 = nullptr, done0 = nullptr;
    static int attr_set = 0;
    if (!attr_set) {
        cudaFuncSetAttribute(lora_gemm_hmma,
                             cudaFuncAttributeMaxDynamicSharedMemorySize, SMEM_DYN);
        cudaFuncSetAttribute(prep_hmma,
                             cudaFuncAttributeMaxDynamicSharedMemorySize, P_SMEM);
        cudaStreamCreateWithFlags(&s1, cudaStreamNonBlocking);
        cudaEventCreateWithFlags(&ev0, cudaEventDisableTiming);
        cudaEventCreateWithFlags(&done0, cudaEventDisableTiming);
        attr_set = 1;
    }

    // side stream: conv_b runs concurrently with chain-0 (both DRAM-bound but
    // chain-0 is small); then GEMM-0 as soon as chunk-0 inputs are ready.
    conv_b_kernel<<<(NCHUNK_B + 255) / 256, 256, 0, s1>>>(base_W, base_B, sub_B);

    // legacy stream: w16 then chunk-0 chain (2048 tokens)
    conv_w_kernel<<<NCHUNK_W / 256, 256>>>(base_A, sub_A, sub_wgate);
    conv_a_kernel<<<(MCH0 * 512) / 256, 256>>>(x, 0);
    {
        dim3 pg(MCH0 / 64, KSPLIT);
        prep_hmma<<<pg, 256, P_SMEM>>>(0);
    }
    combine_kernel<<<(MCH0 * 32) / 256, 256>>>(0);
    cudaEventRecord(ev0, 0);

    // GEMM-0 on side stream (after conv_b in-order, plus chunk-0 chain ready)
    cudaStreamWaitEvent(s1, ev0, 0);
    {
        dim3 gg(OUT_DIM / 128, MCH0 / 128);
        lora_gemm_hmma<<<gg, 256, SMEM_DYN, s1>>>(base_b, out, 0);
    }
    cudaEventRecord(done0, s1);

    // legacy stream: chunk-1 chain (6144 tokens) hides under GEMM-0,
    // then GEMM-1 backfills alongside GEMM-0's tail.
    conv_a_kernel<<<(MCH1 * 512) / 256, 256>>>(x, MCH0);
    {
        dim3 pg(MCH1 / 64, KSPLIT);
        prep_hmma<<<pg, 256, P_SMEM>>>(MCH0);
    }
    combine_kernel<<<(MCH1 * 32) / 256, 256>>>(MCH0);
    {
        dim3 gg(OUT_DIM / 128, MCH1 / 128);
        lora_gemm_hmma<<<gg, 256, SMEM_DYN>>>(base_b, out, MCH0);
    }

    // join
    cudaStreamWaitEvent(0, done0, 0);
}

// round 17
// speedup vs baseline: 1.0356x; 1.0356x over previous
#include <cuda_runtime.h>
#include <cuda_fp16.h>
#include <cstdint>

#define IN_DIM  4096
#define OUT_DIM 4096
#define RANK    16
#define RTOT    80
#define SCALING 2.0f

#define MTOK    8192
#define KPAD    4224        // 4096 + 128 tail (80 used + 48 zero pad)
#define BK      64
#define NKT     (KPAD / BK) // 66

#define MCH     4096        // 2 symmetric M-chunks (R15 proven)

// main GEMM (R4 proven, FROZEN): 128x128 CTA, 8 warps (64x32), 3 stages
#define ASTAGE      16384
#define STAGE_BYTES 32768
#define SMEM_DYN    (3 * STAGE_BYTES)     // 98304 -> 2 CTAs/SM

// prep GEMM: 64x128 CTA tile, 3 stages, K-split 4
#define P_ASTAGE 8192
#define P_STAGE  24576
#define P_SMEM   (3 * P_STAGE)            // 73728
#define KSPLIT   4
#define PKT      ((IN_DIM / BK) / KSPLIT) // 16 kts per split

// ---------------- scratch ----------------------------------------------------
__device__ __align__(16) __half g_a16[(size_t)MTOK    * KPAD];
__device__ __align__(16) __half g_b16[(size_t)OUT_DIM * KPAD];
__device__ __align__(16) __half g_w16[(size_t)128 * IN_DIM];
__device__ __align__(16) float  g_dotp[(size_t)KSPLIT * MTOK * 128];

// ---------------- PTX helpers ------------------------------------------------
__device__ __forceinline__ uint32_t smem_u32(const void* p) {
    uint32_t a;
    asm("{ .reg .u64 t; cvta.to.shared.u64 t, %1; cvt.u32.u64 %0, t; }" : "=r"(a) : "l"(p));
    return a;
}
__device__ __forceinline__ void cp16(uint32_t dst, const void* src) {
    asm volatile("cp.async.cg.shared.global [%0], [%1], 16;" :: "r"(dst), "l"(src));
}
__device__ __forceinline__ void cp_commit() {
    asm volatile("cp.async.commit_group;" ::: "memory");
}
__device__ __forceinline__ void cp_wait1() {
    asm volatile("cp.async.wait_group 1;" ::: "memory");
}
__device__ __forceinline__ void ldsm4(uint32_t* r, uint32_t addr) {
    asm volatile("ldmatrix.sync.aligned.m8n8.x4.shared.b16 {%0,%1,%2,%3}, [%4];"
                 : "=r"(r[0]), "=r"(r[1]), "=r"(r[2]), "=r"(r[3]) : "r"(addr));
}
__device__ __forceinline__ void mma16816(float* d, const uint32_t* a, const uint32_t* b) {
    asm volatile(
        "mma.sync.aligned.m16n8k16.row.col.f32.f16.f16.f32 "
        "{%0,%1,%2,%3}, {%4,%5,%6,%7}, {%8,%9}, {%0,%1,%2,%3};"
        : "+f"(d[0]), "+f"(d[1]), "+f"(d[2]), "+f"(d[3])
        : "r"(a[0]), "r"(a[1]), "r"(a[2]), "r"(a[3]), "r"(b[0]), "r"(b[1]));
}
__device__ __forceinline__ uint4 pack8_h(const float* v) {
    __half2 h01 = __floats2half2_rn(v[0], v[1]);
    __half2 h23 = __floats2half2_rn(v[2], v[3]);
    __half2 h45 = __floats2half2_rn(v[4], v[5]);
    __half2 h67 = __floats2half2_rn(v[6], v[7]);
    uint4 u;
    u.x = *reinterpret_cast<uint32_t*>(&h01);
    u.y = *reinterpret_cast<uint32_t*>(&h23);
    u.z = *reinterpret_cast<uint32_t*>(&h45);
    u.w = *reinterpret_cast<uint32_t*>(&h67);
    return u;
}

// ---------------------------------------------------------------------------
// conv_w: [A|subA|gate] -> g_w16
// ---------------------------------------------------------------------------
#define NCHUNK_W (128 * 512)
__global__ __launch_bounds__(256) void conv_w_kernel(
    const float* __restrict__ base_A,
    const float* __restrict__ sub_A,
    const float* __restrict__ sub_wgate)
{
    int id  = blockIdx.x * 256 + threadIdx.x;
    int row = id >> 9;
    int k   = (id & 511) * 8;
    const float* src = nullptr;
    if (row < 16)      src = &base_A[(size_t)row * IN_DIM + k];
    else if (row < 80) src = &sub_A[(size_t)(row - 16) * IN_DIM + k];
    else if (row < 84) src = &sub_wgate[(size_t)(row - 80) * IN_DIM + k];
    float v[8];
    if (src) {
        float4 v0 = *(const float4*)src;
        float4 v1 = *(const float4*)(src + 4);
        v[0]=v0.x; v[1]=v0.y; v[2]=v0.z; v[3]=v0.w;
        v[4]=v1.x; v[5]=v1.y; v[6]=v1.z; v[7]=v1.w;
    } else {
        #pragma unroll
        for (int q = 0; q < 8; ++q) v[q] = 0.f;
    }
    *(uint4*)&g_w16[(size_t)row * IN_DIM + k] = pack8_h(v);
}

// ---------------------------------------------------------------------------
// conv_b: [W|base_B|sub_B|0] -> g_b16   (side stream; overlaps chain-0)
// ---------------------------------------------------------------------------
#define NCHUNK_B (OUT_DIM * 528)
__global__ __launch_bounds__(256) void conv_b_kernel(
    const float* __restrict__ W,
    const float* __restrict__ base_B,
    const float* __restrict__ sub_B)
{
    int id = blockIdx.x * 256 + threadIdx.x;
    if (id >= NCHUNK_B) return;
    int n = id / 528;
    int k = (id - n * 528) * 8;
    const float* src = nullptr;
    if (k < IN_DIM) {
        src = &W[(size_t)n * IN_DIM + k];
    } else if (k < IN_DIM + RANK) {
        src = &base_B[(size_t)n * RANK + (k - IN_DIM)];
    } else if (k < IN_DIM + RTOT) {
        int kk = k - IN_DIM - RANK;
        int j  = kk >> 4;
        int rr = kk & 15;
        src = &sub_B[((size_t)j * OUT_DIM + n) * RANK + rr];
    }
    float v[8];
    if (src) {
        float4 v0 = *(const float4*)src;
        float4 v1 = *(const float4*)(src + 4);
        v[0]=v0.x; v[1]=v0.y; v[2]=v0.z; v[3]=v0.w;
        v[4]=v1.x; v[5]=v1.y; v[6]=v1.z; v[7]=v1.w;
    } else {
        #pragma unroll
        for (int q = 0; q < 8; ++q) v[q] = 0.f;
    }
    *(uint4*)&g_b16[(size_t)n * KPAD + k] = pack8_h(v);
}

// ---------------------------------------------------------------------------
// conv_a chunk: x[m0:m0+MCH] -> fp16 main columns of g_a16
// ---------------------------------------------------------------------------
__global__ __launch_bounds__(256) void conv_a_kernel(const float* __restrict__ x, int m0)
{
    int id = blockIdx.x * 256 + threadIdx.x;   // MCH * 512
    int m  = m0 + (id >> 9);
    int k  = (id & 511) * 8;
    float v[8];
    float4 v0 = *(const float4*)&x[(size_t)m * IN_DIM + k];
    float4 v1 = *(const float4*)&x[(size_t)m * IN_DIM + k + 4];
    v[0]=v0.x; v[1]=v0.y; v[2]=v0.z; v[3]=v0.w;
    v[4]=v1.x; v[5]=v1.y; v[6]=v1.z; v[7]=v1.w;
    *(uint4*)&g_a16[(size_t)m * KPAD + k] = pack8_h(v);
}

// ---------------------------------------------------------------------------
// prep_hmma chunk, K-split x4: partial dots for tokens [m0, m0+MCH)
// ---------------------------------------------------------------------------
__global__ __launch_bounds__(256, 2) void prep_hmma(int m0)
{
    extern __shared__ __align__(1024) char smem[];
    const uint32_t sb = smem_u32(smem);

    const int tid  = threadIdx.x;
    const int lane = tid & 31;
    const int wid  = tid >> 5;
    const int bm   = m0 + blockIdx.x * 64;
    const int sp   = blockIdx.y;
    const int kt0  = sp * PKT;
    const int wm   = (wid & 1) * 32;
    const int wn   = (wid >> 1) * 32;

    float acc[2][4][4];
    #pragma unroll
    for (int mi = 0; mi < 2; ++mi)
        #pragma unroll
        for (int ni = 0; ni < 4; ++ni)
            #pragma unroll
            for (int q = 0; q < 4; ++q) acc[mi][ni][q] = 0.f;

    const char* gA = (const char*)(g_a16 + (size_t)bm * KPAD);
    const char* gW = (const char*)g_w16;
    const size_t arow_b = (size_t)KPAD * 2;
    const size_t wrow_b = (size_t)IN_DIM * 2;

    const int a_row = tid >> 2;
    const int a_col = (tid & 3) * 16;
    const int b_row = tid >> 1;
    const int b_col = (tid & 1) * 16;

    const int arow  = wm + (lane & 15);
    const int akoff = (lane >> 4) * 16;
    const int apx   = (arow & 7) << 4;
    const int bmat  = lane >> 3;
    const int brow  = wn + (bmat >> 1) * 8 + (lane & 7);
    const int bkoff = (bmat & 1) * 16;
    const int bpx   = (brow & 7) << 4;

#define P_LOAD(s, kt)                                                          \
    {                                                                          \
        const int kb = (kt0 + (kt)) * (BK * 2);                                \
        _Pragma("unroll")                                                      \
        for (int i = 0; i < 2; ++i) {                                          \
            int cb = a_col + i * 64;                                           \
            uint32_t off = a_row * 128 + cb;                                   \
            uint32_t sw  = off ^ ((off >> 3) & 0x70);                          \
            cp16(sb + (s) * P_STAGE + sw, gA + (size_t)a_row * arow_b + kb + cb); \
        }                                                                      \
        _Pragma("unroll")                                                      \
        for (int i = 0; i < 4; ++i) {                                          \
            int cb = b_col + i * 32;                                           \
            uint32_t off = b_row * 128 + cb;                                   \
            uint32_t sw  = off ^ ((off >> 3) & 0x70);                          \
            cp16(sb + (s) * P_STAGE + P_ASTAGE + sw,                           \
                 gW + (size_t)b_row * wrow_b + kb + cb);                       \
        }                                                                      \
        cp_commit();                                                           \
    }

    P_LOAD(0, 0);
    P_LOAD(1, 1);

    for (int kt = 0; kt < PKT; ++kt) {
        cp_wait1();
        __syncthreads();
        if (kt + 2 < PKT) {
            P_LOAD((kt + 2) % 3, kt + 2);
        } else {
            cp_commit();
        }

        const uint32_t sa = sb + (kt % 3) * P_STAGE;
        const uint32_t sB = sa + P_ASTAGE;

        #pragma unroll
        for (int ks = 0; ks < 4; ++ks) {
            const int kb = ks * 32;
            uint32_t a[2][4], b[2][4];
            #pragma unroll
            for (int mi = 0; mi < 2; ++mi)
                ldsm4(a[mi], sa + (uint32_t)(arow + mi * 16) * 128 +
                             (uint32_t)((kb + akoff) ^ apx));
            #pragma unroll
            for (int g = 0; g < 2; ++g)
                ldsm4(b[g], sB + (uint32_t)(brow + g * 16) * 128 +
                            (uint32_t)((kb + bkoff) ^ bpx));
            #pragma unroll
            for (int mi = 0; mi < 2; ++mi) {
                mma16816(acc[mi][0], a[mi], &b[0][0]);
                mma16816(acc[mi][1], a[mi], &b[0][2]);
                mma16816(acc[mi][2], a[mi], &b[1][0]);
                mma16816(acc[mi][3], a[mi], &b[1][2]);
            }
        }
    }
#undef P_LOAD

    float* dout = g_dotp + (size_t)sp * MTOK * 128;
    const int g8 = lane >> 2;
    const int t4 = lane & 3;
    #pragma unroll
    for (int ni = 0; ni < 4; ++ni) {
        const int n = wn + ni * 8 + t4 * 2;
        #pragma unroll
        for (int mi = 0; mi < 2; ++mi) {
            const int m = bm + wm + mi * 16 + g8;
            *(float2*)&dout[(size_t)m * 128 + n]       = make_float2(acc[mi][ni][0], acc[mi][ni][1]);
            *(float2*)&dout[(size_t)(m + 8) * 128 + n] = make_float2(acc[mi][ni][2], acc[mi][ni][3]);
        }
    }
}

// ---------------------------------------------------------------------------
// combine chunk (vectorized): sum partials, gate, write fp16 tail of g_a16
// ---------------------------------------------------------------------------
__global__ __launch_bounds__(256) void combine_kernel(int m0)
{
    int id  = blockIdx.x * 256 + threadIdx.x;    // MCH * 32 quads
    int m   = m0 + (id >> 5);
    int col = (id & 31) * 4;

    __half hv[4];
    if (col < RTOT) {
        float4 d = make_float4(0.f, 0.f, 0.f, 0.f);
        #pragma unroll
        for (int s = 0; s < KSPLIT; ++s) {
            float4 p = *(const float4*)&g_dotp[(size_t)s * MTOK * 128 +
                                               (size_t)m * 128 + col];
            d.x += p.x; d.y += p.y; d.z += p.z; d.w += p.w;
        }
        float gmul = 1.f;
        if (col >= RANK) {
            int gc = 80 + ((col - RANK) >> 4);
            float gt = 0.f;
            #pragma unroll
            for (int s = 0; s < KSPLIT; ++s)
                gt += g_dotp[(size_t)s * MTOK * 128 + (size_t)m * 128 + gc];
            gmul = gt > 0.f ? gt : 0.f;
        }
        const float f = SCALING * gmul;
        hv[0] = __float2half(d.x * f);
        hv[1] = __float2half(d.y * f);
        hv[2] = __float2half(d.z * f);
        hv[3] = __float2half(d.w * f);
    } else {
        hv[0] = hv[1] = hv[2] = hv[3] = __float2half(0.f);
    }
    *(uint2*)&g_a16[(size_t)m * KPAD + IN_DIM + col] = *reinterpret_cast<uint2*>(hv);
}

// ---------------------------------------------------------------------------
// Main HMMA GEMM chunk — FROZEN R4 config, with M offset
// ---------------------------------------------------------------------------
__global__ __launch_bounds__(256, 2) void lora_gemm_hmma(
    const float* __restrict__ bias,
    float* __restrict__ out,
    int m0)
{
    extern __shared__ __align__(1024) char smem[];
    const uint32_t sb = smem_u32(smem);

    const int tid  = threadIdx.x;
    const int lane = tid & 31;
    const int wid  = tid >> 5;
    const int bm   = m0 + blockIdx.y * 128;
    const int bn   = blockIdx.x * 128;
    const int wm   = (wid & 1) * 64;
    const int wn   = (wid >> 1) * 32;

    float acc[4][4][4];
    #pragma unroll
    for (int mi = 0; mi < 4; ++mi)
        #pragma unroll
        for (int ni = 0; ni < 4; ++ni)
            #pragma unroll
            for (int q = 0; q < 4; ++q) acc[mi][ni][q] = 0.f;

    const char* gA = (const char*)(g_a16 + (size_t)bm * KPAD);
    const char* gB = (const char*)(g_b16 + (size_t)bn * KPAD);
    const size_t rowbytes = (size_t)KPAD * 2;

    const int crow = tid >> 3;
    const int ccol = (tid & 7) * 16;

    const int arow  = wm + (lane & 15);
    const int akoff = (lane >> 4) * 16;
    const int apx   = (arow & 7) << 4;
    const int bmat  = lane >> 3;
    const int brow  = wn + (bmat >> 1) * 8 + (lane & 7);
    const int bkoff = (bmat & 1) * 16;
    const int bpx   = (brow & 7) << 4;

#define LOAD_STAGE(s, kt)                                                      \
    {                                                                          \
        const int kb = (kt) * (BK * 2);                                        \
        _Pragma("unroll")                                                      \
        for (int i = 0; i < 4; ++i) {                                          \
            int row = crow + i * 32;                                           \
            uint32_t off = row * 128 + ccol;                                   \
            uint32_t sw  = off ^ ((off >> 3) & 0x70);                          \
            cp16(sb + (s) * STAGE_BYTES + sw, gA + (size_t)row * rowbytes + kb + ccol); \
            cp16(sb + (s) * STAGE_BYTES + ASTAGE + sw,                         \
                 gB + (size_t)row * rowbytes + kb + ccol);                     \
        }                                                                      \
        cp_commit();                                                           \
    }

    LOAD_STAGE(0, 0);
    LOAD_STAGE(1, 1);

    for (int kt = 0; kt < NKT; ++kt) {
        cp_wait1();
        __syncthreads();
        if (kt + 2 < NKT) {
            LOAD_STAGE((kt + 2) % 3, kt + 2);
        } else {
            cp_commit();
        }

        const uint32_t sa = sb + (kt % 3) * STAGE_BYTES;
        const uint32_t sB = sa + ASTAGE;

        #pragma unroll
        for (int ks = 0; ks < 4; ++ks) {
            const int kb = ks * 32;
            uint32_t a[4][4], b[2][4];
            #pragma unroll
            for (int mi = 0; mi < 4; ++mi)
                ldsm4(a[mi], sa + (uint32_t)(arow + mi * 16) * 128 +
                             (uint32_t)((kb + akoff) ^ apx));
            #pragma unroll
            for (int g = 0; g < 2; ++g)
                ldsm4(b[g], sB + (uint32_t)(brow + g * 16) * 128 +
                            (uint32_t)((kb + bkoff) ^ bpx));
            #pragma unroll
            for (int mi = 0; mi < 4; ++mi) {
                mma16816(acc[mi][0], a[mi], &b[0][0]);
                mma16816(acc[mi][1], a[mi], &b[0][2]);
                mma16816(acc[mi][2], a[mi], &b[1][0]);
                mma16816(acc[mi][3], a[mi], &b[1][2]);
            }
        }
    }
#undef LOAD_STAGE

    const int g8 = lane >> 2;
    const int t4 = lane & 3;
    #pragma unroll
    for (int ni = 0; ni < 4; ++ni) {
        const int n = bn + wn + ni * 8 + t4 * 2;
        const float2 bv = *(const float2*)&bias[n];
        #pragma unroll
        for (int mi = 0; mi < 4; ++mi) {
            const int m = bm + wm + mi * 16 + g8;
            float2 o0, o1;
            o0.x = acc[mi][ni][0] + bv.x;
            o0.y = acc[mi][ni][1] + bv.y;
            o1.x = acc[mi][ni][2] + bv.x;
            o1.y = acc[mi][ni][3] + bv.y;
            *(float2*)&out[(size_t)m * OUT_DIM + n]       = o0;
            *(float2*)&out[(size_t)(m + 8) * OUT_DIM + n] = o1;
        }
    }
}

// ---------------------------------------------------------------------------
extern "C" void kernel_launch(void* const* d_in, const int* in_sizes, int n_in,
                              void* d_out, int out_size)
{
    const float* x         = (const float*)d_in[0];
    const float* base_W    = (const float*)d_in[1];
    const float* base_b    = (const float*)d_in[2];
    const float* base_A    = (const float*)d_in[3];
    const float* base_B    = (const float*)d_in[4];
    const float* sub_wgate = (const float*)d_in[5];
    const float* sub_A     = (const float*)d_in[6];
    const float* sub_B     = (const float*)d_in[7];
    float* out = (float*)d_out;

    static cudaStream_t s1 = nullptr;          // single extra stream (guard-safe)
    static cudaEvent_t  ev0 = nullptr, done0 = nullptr;
    static int attr_set = 0;
    if (!attr_set) {
        cudaFuncSetAttribute(lora_gemm_hmma,
                             cudaFuncAttributeMaxDynamicSharedMemorySize, SMEM_DYN);
        cudaFuncSetAttribute(prep_hmma,
                             cudaFuncAttributeMaxDynamicSharedMemorySize, P_SMEM);
        cudaStreamCreateWithFlags(&s1, cudaStreamNonBlocking);
        cudaEventCreateWithFlags(&ev0, cudaEventDisableTiming);
        cudaEventCreateWithFlags(&done0, cudaEventDisableTiming);
        attr_set = 1;
    }

    dim3 pgrid(MCH / 64, KSPLIT);
    dim3 ggrid(OUT_DIM / 128, MCH / 128);

    // side stream: conv_b overlaps chain-0; GEMM-0 follows in-order once ev0 fires
    conv_b_kernel<<<(NCHUNK_B + 255) / 256, 256, 0, s1>>>(base_W, base_B, sub_B);

    // legacy stream: w16 then chunk-0 chain (4096 tokens)
    conv_w_kernel<<<NCHUNK_W / 256, 256>>>(base_A, sub_A, sub_wgate);
    conv_a_kernel<<<(MCH * 512) / 256, 256>>>(x, 0);
    prep_hmma<<<pgrid, 256, P_SMEM>>>(0);
    combine_kernel<<<(MCH * 32) / 256, 256>>>(0);
    cudaEventRecord(ev0, 0);

    // GEMM-0 on side stream (conv_b done in-order; chunk-0 inputs ready via ev0)
    cudaStreamWaitEvent(s1, ev0, 0);
    lora_gemm_hmma<<<ggrid, 256, SMEM_DYN, s1>>>(base_b, out, 0);
    cudaEventRecord(done0, s1);

    // legacy stream: chunk-1 chain hides under GEMM-0, then GEMM-1 backfills
    conv_a_kernel<<<(MCH * 512) / 256, 256>>>(x, MCH);
    prep_hmma<<<pgrid, 256, P_SMEM>>>(MCH);
    combine_kernel<<<(MCH * 32) / 256, 256>>>(MCH);
    lora_gemm_hmma<<<ggrid, 256, SMEM_DYN>>>(base_b, out, MCH);

    // join chunk-0 GEMM back into the legacy stream
    cudaStreamWaitEvent(0, done0, 0);
}